// round 1
// baseline (speedup 1.0000x reference)
#include <cuda_runtime.h>
#include <math.h>

// Problem dims (fixed for this problem instance)
#define Bdim 2
#define Mdim 2048
#define Ndim 2048
#define Edim 128
#define Kdim 8
#define Ddim 16
#define NHEAD (Bdim * Kdim)
#define BN 128   // queries per flash block
#define TM 128   // key tile rows

// Static scratch (allocation-free rule): Q/K/V laid out [head][seq][d], O laid out [b][n][k][d]
__device__ float g_Q[NHEAD * (size_t)Ndim * Ddim];
__device__ float g_K[NHEAD * (size_t)Mdim * Ddim];
__device__ float g_V[NHEAD * (size_t)Mdim * Ddim];
__device__ float g_O[Bdim * (size_t)Ndim * Kdim * Ddim];

// ---------------------------------------------------------------------------
// Kernel 1: fused projections.
//   K[b,k,m,d] = sum_e x[b,m,e] * lambda1[k,e,d] + bias_lambda[k,d]
//   V[b,k,m,d] = sum_e x[b,m,e] * theta1 [k,e,d]          (bias_theta added later)
//   Q[b,k,n,d] = sum_e y[b,n,e] * lambda2[k,e,d]
// Block = 128 threads, handles 4 rows. warp w -> row, lane -> (k, d-quad).
// Weight loads are float4 and fully coalesced across the warp.
// ---------------------------------------------------------------------------
__global__ void proj_kernel(const float* __restrict__ x, const float* __restrict__ y,
                            const float* __restrict__ l1, const float* __restrict__ l2,
                            const float* __restrict__ t1, const float* __restrict__ bl)
{
    __shared__ float xs[4][Edim];
    __shared__ float ys[4][Edim];
    const int tid  = threadIdx.x;          // 0..127
    const int w    = tid >> 5;             // warp = which of 4 rows
    const int lane = tid & 31;
    const int row0 = blockIdx.x * 4;

    // Cooperative load of 4 x-rows and 4 y-rows (rows are contiguous).
    #pragma unroll
    for (int i = tid; i < 4 * Edim; i += 128) {
        xs[i >> 7][i & 127] = x[row0 * Edim + i];
        ys[i >> 7][i & 127] = y[row0 * Edim + i];
    }
    __syncthreads();

    const int row = row0 + w;
    const int b   = row / Mdim;
    const int m   = row % Mdim;
    const int k   = lane >> 2;     // head 0..7
    const int dq  = lane & 3;      // d-quad 0..3 (d = 4*dq .. 4*dq+3)

    const float4* l1v = reinterpret_cast<const float4*>(l1);
    const float4* l2v = reinterpret_cast<const float4*>(l2);
    const float4* t1v = reinterpret_cast<const float4*>(t1);

    float4 ka = make_float4(0.f, 0.f, 0.f, 0.f);
    float4 va = make_float4(0.f, 0.f, 0.f, 0.f);
    float4 qa = make_float4(0.f, 0.f, 0.f, 0.f);

    #pragma unroll 4
    for (int e = 0; e < Edim; e++) {
        const float xv = xs[w][e];
        const float yv = ys[w][e];
        const int wi = (k * Edim + e) * 4 + dq;   // float4 index into [k,e,d]
        float4 a = l1v[wi];
        ka.x += xv * a.x; ka.y += xv * a.y; ka.z += xv * a.z; ka.w += xv * a.w;
        float4 c = t1v[wi];
        va.x += xv * c.x; va.y += xv * c.y; va.z += xv * c.z; va.w += xv * c.w;
        float4 q = l2v[wi];
        qa.x += yv * q.x; qa.y += yv * q.y; qa.z += yv * q.z; qa.w += yv * q.w;
    }

    // bias_lambda into K
    const float4 bb = reinterpret_cast<const float4*>(bl)[k * 4 + dq];
    ka.x += bb.x; ka.y += bb.y; ka.z += bb.z; ka.w += bb.w;

    const int head = b * Kdim + k;
    const size_t idx = (((size_t)head * Mdim + m) * Ddim + dq * 4) / 4;
    reinterpret_cast<float4*>(g_K)[idx] = ka;
    reinterpret_cast<float4*>(g_V)[idx] = va;
    reinterpret_cast<float4*>(g_Q)[idx] = qa;   // N == M so same indexing
}

// ---------------------------------------------------------------------------
// Kernel 2: flash attention, fp32.
//   For each (head = b*8+k, n): logits over m = Q[n]·K[m] * 0.25, softmax over m,
//   O[n] = sum_m p[m] * V[m], then /l and + bias_theta.
// Block: 128 threads = 128 queries; loop over 128-row K/V tiles in smem.
// Online softmax processed in chunks of 8 to amortize the max/rescale.
// ---------------------------------------------------------------------------
__global__ void flash_kernel(const float* __restrict__ bt)
{
    __shared__ float Ks[TM * Ddim];
    __shared__ float Vs[TM * Ddim];

    const int head  = blockIdx.y;                  // 0..15
    const int ntile = blockIdx.x;
    const int tid   = threadIdx.x;
    const int n     = ntile * BN + tid;

    // Load and pre-scale q (scale = head_dim^-0.5 = 0.25)
    const float4* qp = reinterpret_cast<const float4*>(g_Q + ((size_t)head * Ndim + n) * Ddim);
    float4 q0 = qp[0], q1 = qp[1], q2 = qp[2], q3 = qp[3];
    const float scale = 0.25f;
    q0.x *= scale; q0.y *= scale; q0.z *= scale; q0.w *= scale;
    q1.x *= scale; q1.y *= scale; q1.z *= scale; q1.w *= scale;
    q2.x *= scale; q2.y *= scale; q2.z *= scale; q2.w *= scale;
    q3.x *= scale; q3.y *= scale; q3.z *= scale; q3.w *= scale;

    float o[Ddim];
    #pragma unroll
    for (int d = 0; d < Ddim; d++) o[d] = 0.f;
    float mi = -INFINITY, li = 0.f;

    const float4* Kg4 = reinterpret_cast<const float4*>(g_K + (size_t)head * Mdim * Ddim);
    const float4* Vg4 = reinterpret_cast<const float4*>(g_V + (size_t)head * Mdim * Ddim);
    float4* Ks4 = reinterpret_cast<float4*>(Ks);
    float4* Vs4 = reinterpret_cast<float4*>(Vs);

    for (int m0 = 0; m0 < Mdim; m0 += TM) {
        __syncthreads();
        const int base4 = m0 * Ddim / 4;
        #pragma unroll
        for (int i = 0; i < 4; i++) {
            Ks4[tid + i * 128] = Kg4[base4 + tid + i * 128];
            Vs4[tid + i * 128] = Vg4[base4 + tid + i * 128];
        }
        __syncthreads();

        #pragma unroll 1
        for (int j0 = 0; j0 < TM; j0 += 8) {
            float s[8];
            #pragma unroll
            for (int jj = 0; jj < 8; jj++) {
                const float4* kr = reinterpret_cast<const float4*>(Ks + (j0 + jj) * Ddim);
                const float4 a = kr[0], bb = kr[1], c = kr[2], dd = kr[3];
                s[jj] = q0.x * a.x  + q0.y * a.y  + q0.z * a.z  + q0.w * a.w
                      + q1.x * bb.x + q1.y * bb.y + q1.z * bb.z + q1.w * bb.w
                      + q2.x * c.x  + q2.y * c.y  + q2.z * c.z  + q2.w * c.w
                      + q3.x * dd.x + q3.y * dd.y + q3.z * dd.z + q3.w * dd.w;
            }
            float mc = s[0];
            #pragma unroll
            for (int jj = 1; jj < 8; jj++) mc = fmaxf(mc, s[jj]);
            const float mnew = fmaxf(mi, mc);
            const float corr = __expf(mi - mnew);
            li *= corr;
            #pragma unroll
            for (int d = 0; d < Ddim; d++) o[d] *= corr;
            #pragma unroll
            for (int jj = 0; jj < 8; jj++) {
                const float p = __expf(s[jj] - mnew);
                li += p;
                const float4* vr = reinterpret_cast<const float4*>(Vs + (j0 + jj) * Ddim);
                const float4 a = vr[0], bb = vr[1], c = vr[2], dd = vr[3];
                o[0]  += p * a.x;  o[1]  += p * a.y;  o[2]  += p * a.z;  o[3]  += p * a.w;
                o[4]  += p * bb.x; o[5]  += p * bb.y; o[6]  += p * bb.z; o[7]  += p * bb.w;
                o[8]  += p * c.x;  o[9]  += p * c.y;  o[10] += p * c.z;  o[11] += p * c.w;
                o[12] += p * dd.x; o[13] += p * dd.y; o[14] += p * dd.z; o[15] += p * dd.w;
            }
            mi = mnew;
        }
    }

    // Epilogue: normalize, add bias_theta (sum_m att = 1, but add after sum, exact same)
    const int b = head / Kdim;
    const int k = head % Kdim;
    const float inv = 1.f / li;
    float* Op = g_O + (((size_t)b * Ndim + n) * Kdim + k) * Ddim;
    float4 r[4];
    #pragma unroll
    for (int i = 0; i < 4; i++) {
        r[i].x = o[4 * i + 0] * inv + bt[k * Ddim + 4 * i + 0];
        r[i].y = o[4 * i + 1] * inv + bt[k * Ddim + 4 * i + 1];
        r[i].z = o[4 * i + 2] * inv + bt[k * Ddim + 4 * i + 2];
        r[i].w = o[4 * i + 3] * inv + bt[k * Ddim + 4 * i + 3];
        reinterpret_cast<float4*>(Op)[i] = r[i];
    }
}

// ---------------------------------------------------------------------------
// Kernel 3: output projection. out[b,n,e] = sum_{k,d} O[b,n,k,d] * theta2[k,e,d]
// Block per (b,n) row, thread per e. theta2 is 64KB -> lives in L1/L2.
// ---------------------------------------------------------------------------
__global__ void out_kernel(const float* __restrict__ t2, float* __restrict__ out)
{
    __shared__ float orow[Kdim * Ddim];   // 128 floats
    const int row = blockIdx.x;           // b*N + n
    const int e = threadIdx.x;            // 0..127
    orow[e] = g_O[(size_t)row * (Kdim * Ddim) + e];
    __syncthreads();

    float acc = 0.f;
    const float4* t2v = reinterpret_cast<const float4*>(t2);
    #pragma unroll
    for (int k = 0; k < Kdim; k++) {
        const int base = (k * Edim + e) * 4;   // float4 index of theta2[k][e][0]
        #pragma unroll
        for (int dq = 0; dq < 4; dq++) {
            const float4 wv = t2v[base + dq];
            const float* oo = &orow[k * Ddim + dq * 4];
            acc += wv.x * oo[0] + wv.y * oo[1] + wv.z * oo[2] + wv.w * oo[3];
        }
    }
    out[(size_t)row * Edim + e] = acc;
}

extern "C" void kernel_launch(void* const* d_in, const int* in_sizes, int n_in,
                              void* d_out, int out_size)
{
    const float* x  = (const float*)d_in[0];
    const float* y  = (const float*)d_in[1];
    const float* l1 = (const float*)d_in[2];
    const float* l2 = (const float*)d_in[3];
    const float* t1 = (const float*)d_in[4];
    const float* t2 = (const float*)d_in[5];
    const float* bl = (const float*)d_in[6];
    const float* bt = (const float*)d_in[7];

    proj_kernel<<<Bdim * Mdim / 4, 128>>>(x, y, l1, l2, t1, bl);
    flash_kernel<<<dim3(Ndim / BN, NHEAD), 128>>>(bt);
    out_kernel<<<Bdim * Ndim, 128>>>(t2, (float*)d_out);
}

// round 2
// speedup vs baseline: 1.2157x; 1.2157x over previous
#include <cuda_runtime.h>
#include <math.h>

// Problem dims (fixed)
#define Bdim 2
#define Mdim 2048
#define Ndim 2048
#define Edim 128
#define Kdim 8
#define Ddim 16
#define NHEAD (Bdim * Kdim)
#define BN 256   // queries per flash block (== blockDim)
#define TM 128   // key tile rows

// Static scratch: Q/K/V [head][seq][d], O [b][n][k][d]
__device__ float g_Q[NHEAD * (size_t)Ndim * Ddim];
__device__ float g_K[NHEAD * (size_t)Mdim * Ddim];
__device__ float g_V[NHEAD * (size_t)Mdim * Ddim];
__device__ float g_O[Bdim * (size_t)Ndim * Kdim * Ddim];

// ---- packed f32x2 helpers (FFMA2/FMUL2 — only reachable via PTX) ----
__device__ __forceinline__ double fma2(double a, double b, double c) {
    double d; asm("fma.rn.f32x2 %0, %1, %2, %3;" : "=d"(d) : "d"(a), "d"(b), "d"(c)); return d;
}
__device__ __forceinline__ double mul2(double a, double b) {
    double d; asm("mul.rn.f32x2 %0, %1, %2;" : "=d"(d) : "d"(a), "d"(b)); return d;
}
__device__ __forceinline__ float ex2f(float x) {
    float r; asm("ex2.approx.f32 %0, %1;" : "=f"(r) : "f"(x)); return r;
}
__device__ __forceinline__ float lo2(double d) { return __int_as_float(__double2loint(d)); }
__device__ __forceinline__ float hi2(double d) { return __int_as_float(__double2hiint(d)); }
__device__ __forceinline__ double pk2(float lo, float hi) {
    return __hiloint2double(__float_as_int(hi), __float_as_int(lo));
}

// ---------------------------------------------------------------------------
// Kernel 1: fused projections, register-blocked 4 rows/warp (16 rows/block).
//   K[b,k,m,d] = x·lambda1 + bias_lambda ; V = x·theta1 ; Q = y·lambda2
// Each weight float4 load now feeds 4 rows -> 4x less L1 weight traffic.
// ---------------------------------------------------------------------------
__global__ __launch_bounds__(128) void proj_kernel(
    const float* __restrict__ x, const float* __restrict__ y,
    const float* __restrict__ l1, const float* __restrict__ l2,
    const float* __restrict__ t1, const float* __restrict__ bl)
{
    __shared__ float xs[16][Edim];
    __shared__ float ys[16][Edim];
    const int tid  = threadIdx.x;
    const int w    = tid >> 5;
    const int lane = tid & 31;
    const int row0 = blockIdx.x * 16;

    #pragma unroll
    for (int i = tid; i < 16 * Edim; i += 128) {
        xs[i >> 7][i & 127] = x[row0 * Edim + i];
        ys[i >> 7][i & 127] = y[row0 * Edim + i];
    }
    __syncthreads();

    const int k  = lane >> 2;      // head 0..7
    const int dq = lane & 3;       // d-quad

    const float4* l1v = reinterpret_cast<const float4*>(l1);
    const float4* l2v = reinterpret_cast<const float4*>(l2);
    const float4* t1v = reinterpret_cast<const float4*>(t1);

    float4 ka[4], va[4], qa[4];
    #pragma unroll
    for (int r = 0; r < 4; r++) {
        ka[r] = make_float4(0.f,0.f,0.f,0.f);
        va[r] = make_float4(0.f,0.f,0.f,0.f);
        qa[r] = make_float4(0.f,0.f,0.f,0.f);
    }

    #pragma unroll 2
    for (int e = 0; e < Edim; e++) {
        const int wi = (k * Edim + e) * 4 + dq;
        const float4 A = l1v[wi];
        const float4 C = t1v[wi];
        const float4 Qw = l2v[wi];
        #pragma unroll
        for (int r = 0; r < 4; r++) {
            const float xv = xs[w * 4 + r][e];
            const float yv = ys[w * 4 + r][e];
            ka[r].x += xv * A.x;  ka[r].y += xv * A.y;  ka[r].z += xv * A.z;  ka[r].w += xv * A.w;
            va[r].x += xv * C.x;  va[r].y += xv * C.y;  va[r].z += xv * C.z;  va[r].w += xv * C.w;
            qa[r].x += yv * Qw.x; qa[r].y += yv * Qw.y; qa[r].z += yv * Qw.z; qa[r].w += yv * Qw.w;
        }
    }

    const float4 bb = reinterpret_cast<const float4*>(bl)[k * 4 + dq];
    #pragma unroll
    for (int r = 0; r < 4; r++) {
        ka[r].x += bb.x; ka[r].y += bb.y; ka[r].z += bb.z; ka[r].w += bb.w;
        const int row = row0 + w * 4 + r;
        const int b   = row / Mdim;
        const int m   = row % Mdim;
        const int head = b * Kdim + k;
        const size_t idx = (((size_t)head * Mdim + m) * Ddim + dq * 4) / 4;
        reinterpret_cast<float4*>(g_K)[idx] = ka[r];
        reinterpret_cast<float4*>(g_V)[idx] = va[r];
        reinterpret_cast<float4*>(g_Q)[idx] = qa[r];
    }
}

// ---------------------------------------------------------------------------
// Kernel 2: flash attention, packed f32x2 math.
// Block = 256 threads = 256 queries; grid = (2048/256, 16) = 128 blocks -> 1 wave.
// logits in log2 domain: q pre-scaled by 0.25*log2(e); exp via ex2.approx.
// ---------------------------------------------------------------------------
__global__ __launch_bounds__(BN) void flash_kernel(const float* __restrict__ bt)
{
    __shared__ __align__(16) float Ks[TM * Ddim];
    __shared__ __align__(16) float Vs[TM * Ddim];

    const int head = blockIdx.y;
    const int tid  = threadIdx.x;
    const int n    = blockIdx.x * BN + tid;

    const float sc = 0.25f * 1.4426950408889634f;   // head_dim^-1/2 * log2(e)
    const float4* qp = reinterpret_cast<const float4*>(g_Q + ((size_t)head * Ndim + n) * Ddim);
    double q2[8];
    #pragma unroll
    for (int i = 0; i < 4; i++) {
        const float4 v = qp[i];
        q2[2*i]   = pk2(v.x * sc, v.y * sc);
        q2[2*i+1] = pk2(v.z * sc, v.w * sc);
    }

    double o2[8];
    #pragma unroll
    for (int i = 0; i < 8; i++) o2[i] = 0.0;   // packed {0,0}
    float mi = -INFINITY, li = 0.f;

    const float4* Kg4 = reinterpret_cast<const float4*>(g_K + (size_t)head * Mdim * Ddim);
    const float4* Vg4 = reinterpret_cast<const float4*>(g_V + (size_t)head * Mdim * Ddim);
    float4* Ks4 = reinterpret_cast<float4*>(Ks);
    float4* Vs4 = reinterpret_cast<float4*>(Vs);

    for (int m0 = 0; m0 < Mdim; m0 += TM) {
        __syncthreads();
        const int base4 = m0 * Ddim / 4;
        #pragma unroll
        for (int i = 0; i < 2; i++) {
            Ks4[tid + i * BN] = Kg4[base4 + tid + i * BN];
            Vs4[tid + i * BN] = Vg4[base4 + tid + i * BN];
        }
        __syncthreads();

        #pragma unroll 1
        for (int j0 = 0; j0 < TM; j0 += 8) {
            float s[8];
            #pragma unroll
            for (int jj = 0; jj < 8; jj++) {
                const double2* kr = reinterpret_cast<const double2*>(Ks + (j0 + jj) * Ddim);
                const double2 a = kr[0], b = kr[1], c = kr[2], d = kr[3];
                double acc = mul2(q2[0], a.x);
                acc = fma2(q2[1], a.y, acc);
                acc = fma2(q2[2], b.x, acc);
                acc = fma2(q2[3], b.y, acc);
                acc = fma2(q2[4], c.x, acc);
                acc = fma2(q2[5], c.y, acc);
                acc = fma2(q2[6], d.x, acc);
                acc = fma2(q2[7], d.y, acc);
                s[jj] = lo2(acc) + hi2(acc);
            }
            float mc = s[0];
            #pragma unroll
            for (int jj = 1; jj < 8; jj++) mc = fmaxf(mc, s[jj]);
            const float mnew = fmaxf(mi, mc);
            const float corr = ex2f(mi - mnew);
            li *= corr;
            const double corr2 = pk2(corr, corr);
            #pragma unroll
            for (int i = 0; i < 8; i++) o2[i] = mul2(corr2, o2[i]);
            #pragma unroll
            for (int jj = 0; jj < 8; jj++) {
                const float p = ex2f(s[jj] - mnew);
                li += p;
                const double p2 = pk2(p, p);
                const double2* vr = reinterpret_cast<const double2*>(Vs + (j0 + jj) * Ddim);
                const double2 a = vr[0], b = vr[1], c = vr[2], d = vr[3];
                o2[0] = fma2(p2, a.x, o2[0]);
                o2[1] = fma2(p2, a.y, o2[1]);
                o2[2] = fma2(p2, b.x, o2[2]);
                o2[3] = fma2(p2, b.y, o2[3]);
                o2[4] = fma2(p2, c.x, o2[4]);
                o2[5] = fma2(p2, c.y, o2[5]);
                o2[6] = fma2(p2, d.x, o2[6]);
                o2[7] = fma2(p2, d.y, o2[7]);
            }
            mi = mnew;
        }
    }

    const int b = head / Kdim;
    const int k = head % Kdim;
    const float inv = 1.f / li;
    float* Op = g_O + (((size_t)b * Ndim + n) * Kdim + k) * Ddim;
    #pragma unroll
    for (int i = 0; i < 4; i++) {
        float4 r;
        r.x = lo2(o2[2*i])   * inv + bt[k * Ddim + 4*i + 0];
        r.y = hi2(o2[2*i])   * inv + bt[k * Ddim + 4*i + 1];
        r.z = lo2(o2[2*i+1]) * inv + bt[k * Ddim + 4*i + 2];
        r.w = hi2(o2[2*i+1]) * inv + bt[k * Ddim + 4*i + 3];
        reinterpret_cast<float4*>(Op)[i] = r;
    }
}

// ---------------------------------------------------------------------------
// Kernel 3: output projection, register-blocked 8 rows/block.
//   out[b,n,e] = sum_{k,d} O[b,n,k,d] * theta2[k,e,d]
// Each theta2 float4 load feeds 8 rows -> 8x less (badly-coalesced) L1 traffic.
// ---------------------------------------------------------------------------
__global__ __launch_bounds__(128) void out_kernel(const float* __restrict__ t2,
                                                  float* __restrict__ out)
{
    __shared__ __align__(16) float orow[8][Kdim * Ddim];
    const int row0 = blockIdx.x * 8;
    const int e = threadIdx.x;   // 0..127

    #pragma unroll
    for (int r = 0; r < 8; r++)
        orow[r][e] = g_O[(size_t)(row0 + r) * (Kdim * Ddim) + e];
    __syncthreads();

    float acc[8];
    #pragma unroll
    for (int r = 0; r < 8; r++) acc[r] = 0.f;

    const float4* t2v = reinterpret_cast<const float4*>(t2);
    #pragma unroll
    for (int k = 0; k < Kdim; k++) {
        const int base = (k * Edim + e) * 4;
        #pragma unroll
        for (int dq = 0; dq < 4; dq++) {
            const float4 wv = t2v[base + dq];
            #pragma unroll
            for (int r = 0; r < 8; r++) {
                const float4 oo = *reinterpret_cast<const float4*>(&orow[r][k * Ddim + dq * 4]);
                acc[r] += wv.x * oo.x + wv.y * oo.y + wv.z * oo.z + wv.w * oo.w;
            }
        }
    }
    #pragma unroll
    for (int r = 0; r < 8; r++)
        out[(size_t)(row0 + r) * Edim + e] = acc[r];
}

extern "C" void kernel_launch(void* const* d_in, const int* in_sizes, int n_in,
                              void* d_out, int out_size)
{
    const float* x  = (const float*)d_in[0];
    const float* y  = (const float*)d_in[1];
    const float* l1 = (const float*)d_in[2];
    const float* l2 = (const float*)d_in[3];
    const float* t1 = (const float*)d_in[4];
    const float* t2 = (const float*)d_in[5];
    const float* bl = (const float*)d_in[6];
    const float* bt = (const float*)d_in[7];

    proj_kernel<<<Bdim * Mdim / 16, 128>>>(x, y, l1, l2, t1, bl);
    flash_kernel<<<dim3(Ndim / BN, NHEAD), BN>>>(bt);
    out_kernel<<<Bdim * Ndim / 8, 128>>>(t2, (float*)d_out);
}

// round 3
// speedup vs baseline: 1.4634x; 1.2038x over previous
#include <cuda_runtime.h>
#include <math.h>

// Problem dims (fixed)
#define Bdim 2
#define Mdim 2048
#define Ndim 2048
#define Edim 128
#define Kdim 8
#define Ddim 16
#define NHEAD (Bdim * Kdim)
#define BN 128            // queries per flash block
#define TM 128            // key tile rows in smem
#define SPLIT 4           // key-axis splits
#define MCHUNK (Mdim / SPLIT)

// Static scratch: Q/K/V [head][seq][d], O [b][n][k][d], split partials
__device__ float g_Q[NHEAD * (size_t)Ndim * Ddim];
__device__ float g_K[NHEAD * (size_t)Mdim * Ddim];
__device__ float g_V[NHEAD * (size_t)Mdim * Ddim];
__device__ float g_O[Bdim * (size_t)Ndim * Kdim * Ddim];
__device__ float g_Po[NHEAD * (size_t)SPLIT * Ndim * Ddim];   // unnormalized partial o
__device__ float g_Pm[NHEAD * (size_t)SPLIT * Ndim];          // partial max (log2 domain)
__device__ float g_Pl[NHEAD * (size_t)SPLIT * Ndim];          // partial sum

// ---- packed f32x2 helpers (FFMA2/FMUL2 — only reachable via PTX) ----
__device__ __forceinline__ double fma2(double a, double b, double c) {
    double d; asm("fma.rn.f32x2 %0, %1, %2, %3;" : "=d"(d) : "d"(a), "d"(b), "d"(c)); return d;
}
__device__ __forceinline__ double mul2(double a, double b) {
    double d; asm("mul.rn.f32x2 %0, %1, %2;" : "=d"(d) : "d"(a), "d"(b)); return d;
}
__device__ __forceinline__ float ex2f(float x) {
    float r; asm("ex2.approx.f32 %0, %1;" : "=f"(r) : "f"(x)); return r;
}
__device__ __forceinline__ float lo2(double d) { return __int_as_float(__double2loint(d)); }
__device__ __forceinline__ float hi2(double d) { return __int_as_float(__double2hiint(d)); }
__device__ __forceinline__ double pk2(float lo, float hi) {
    return __hiloint2double(__float_as_int(hi), __float_as_int(lo));
}

// ---------------------------------------------------------------------------
// Kernel 1: fused projections. 256 threads, 8 warps, 2 rows/warp = 16 rows/block.
// Grid = 256 blocks -> 2048 warps for latency hiding on L2 weight loads.
// ---------------------------------------------------------------------------
__global__ __launch_bounds__(256) void proj_kernel(
    const float* __restrict__ x, const float* __restrict__ y,
    const float* __restrict__ l1, const float* __restrict__ l2,
    const float* __restrict__ t1, const float* __restrict__ bl)
{
    __shared__ float xs[16][Edim];
    __shared__ float ys[16][Edim];
    const int tid  = threadIdx.x;          // 0..255
    const int w    = tid >> 5;             // warp 0..7
    const int lane = tid & 31;
    const int row0 = blockIdx.x * 16;

    // Coalesced float4 staging of 16 x-rows and 16 y-rows
    {
        const float4* xg = reinterpret_cast<const float4*>(x + (size_t)row0 * Edim);
        const float4* yg = reinterpret_cast<const float4*>(y + (size_t)row0 * Edim);
        float4* xs4 = reinterpret_cast<float4*>(&xs[0][0]);
        float4* ys4 = reinterpret_cast<float4*>(&ys[0][0]);
        #pragma unroll
        for (int i = 0; i < 2; i++) {
            xs4[tid + i * 256] = xg[tid + i * 256];
            ys4[tid + i * 256] = yg[tid + i * 256];
        }
    }
    __syncthreads();

    const int k  = lane >> 2;      // head 0..7
    const int dq = lane & 3;       // d-quad

    const float4* l1v = reinterpret_cast<const float4*>(l1);
    const float4* l2v = reinterpret_cast<const float4*>(l2);
    const float4* t1v = reinterpret_cast<const float4*>(t1);

    float4 ka[2], va[2], qa[2];
    #pragma unroll
    for (int r = 0; r < 2; r++) {
        ka[r] = make_float4(0.f,0.f,0.f,0.f);
        va[r] = make_float4(0.f,0.f,0.f,0.f);
        qa[r] = make_float4(0.f,0.f,0.f,0.f);
    }

    #pragma unroll 4
    for (int e = 0; e < Edim; e++) {
        const int wi = (k * Edim + e) * 4 + dq;
        const float4 A  = l1v[wi];
        const float4 C  = t1v[wi];
        const float4 Qw = l2v[wi];
        #pragma unroll
        for (int r = 0; r < 2; r++) {
            const float xv = xs[w * 2 + r][e];
            const float yv = ys[w * 2 + r][e];
            ka[r].x += xv * A.x;  ka[r].y += xv * A.y;  ka[r].z += xv * A.z;  ka[r].w += xv * A.w;
            va[r].x += xv * C.x;  va[r].y += xv * C.y;  va[r].z += xv * C.z;  va[r].w += xv * C.w;
            qa[r].x += yv * Qw.x; qa[r].y += yv * Qw.y; qa[r].z += yv * Qw.z; qa[r].w += yv * Qw.w;
        }
    }

    const float4 bb = reinterpret_cast<const float4*>(bl)[k * 4 + dq];
    #pragma unroll
    for (int r = 0; r < 2; r++) {
        ka[r].x += bb.x; ka[r].y += bb.y; ka[r].z += bb.z; ka[r].w += bb.w;
        const int row = row0 + w * 2 + r;
        const int b   = row / Mdim;
        const int m   = row % Mdim;
        const int head = b * Kdim + k;
        const size_t idx = (((size_t)head * Mdim + m) * Ddim + dq * 4) / 4;
        reinterpret_cast<float4*>(g_K)[idx] = ka[r];
        reinterpret_cast<float4*>(g_V)[idx] = va[r];
        reinterpret_cast<float4*>(g_Q)[idx] = qa[r];
    }
}

// ---------------------------------------------------------------------------
// Kernel 2: flash attention, split-K over the key axis, packed f32x2 math.
// Grid = (16 n-tiles, 16 heads, 4 splits) = 1024 blocks x 4 warps = 4096 warps.
// Each block covers 512 keys; writes unnormalized partial (o, m, l).
// ---------------------------------------------------------------------------
__global__ __launch_bounds__(BN) void flash_kernel()
{
    __shared__ __align__(16) float Ks[TM * Ddim];
    __shared__ __align__(16) float Vs[TM * Ddim];

    const int head = blockIdx.y;
    const int sp   = blockIdx.z;
    const int tid  = threadIdx.x;
    const int n    = blockIdx.x * BN + tid;

    const float sc = 0.25f * 1.4426950408889634f;   // head_dim^-1/2 * log2(e)
    const float4* qp = reinterpret_cast<const float4*>(g_Q + ((size_t)head * Ndim + n) * Ddim);
    double q2[8];
    #pragma unroll
    for (int i = 0; i < 4; i++) {
        const float4 v = qp[i];
        q2[2*i]   = pk2(v.x * sc, v.y * sc);
        q2[2*i+1] = pk2(v.z * sc, v.w * sc);
    }

    double o2[8];
    #pragma unroll
    for (int i = 0; i < 8; i++) o2[i] = 0.0;
    float mi = -INFINITY, li = 0.f;

    const int mbeg = sp * MCHUNK;
    const float4* Kg4 = reinterpret_cast<const float4*>(g_K + (size_t)head * Mdim * Ddim);
    const float4* Vg4 = reinterpret_cast<const float4*>(g_V + (size_t)head * Mdim * Ddim);
    float4* Ks4 = reinterpret_cast<float4*>(Ks);
    float4* Vs4 = reinterpret_cast<float4*>(Vs);

    for (int m0 = mbeg; m0 < mbeg + MCHUNK; m0 += TM) {
        __syncthreads();
        const int base4 = m0 * Ddim / 4;
        #pragma unroll
        for (int i = 0; i < 4; i++) {
            Ks4[tid + i * BN] = Kg4[base4 + tid + i * BN];
            Vs4[tid + i * BN] = Vg4[base4 + tid + i * BN];
        }
        __syncthreads();

        #pragma unroll 1
        for (int j0 = 0; j0 < TM; j0 += 8) {
            float s[8];
            #pragma unroll
            for (int jj = 0; jj < 8; jj++) {
                const double2* kr = reinterpret_cast<const double2*>(Ks + (j0 + jj) * Ddim);
                const double2 a = kr[0], b = kr[1], c = kr[2], d = kr[3];
                double acc = mul2(q2[0], a.x);
                acc = fma2(q2[1], a.y, acc);
                acc = fma2(q2[2], b.x, acc);
                acc = fma2(q2[3], b.y, acc);
                acc = fma2(q2[4], c.x, acc);
                acc = fma2(q2[5], c.y, acc);
                acc = fma2(q2[6], d.x, acc);
                acc = fma2(q2[7], d.y, acc);
                s[jj] = lo2(acc) + hi2(acc);
            }
            float mc = s[0];
            #pragma unroll
            for (int jj = 1; jj < 8; jj++) mc = fmaxf(mc, s[jj]);
            const float mnew = fmaxf(mi, mc);
            const float corr = ex2f(mi - mnew);
            li *= corr;
            const double corr2 = pk2(corr, corr);
            #pragma unroll
            for (int i = 0; i < 8; i++) o2[i] = mul2(corr2, o2[i]);
            #pragma unroll
            for (int jj = 0; jj < 8; jj++) {
                const float p = ex2f(s[jj] - mnew);
                li += p;
                const double p2 = pk2(p, p);
                const double2* vr = reinterpret_cast<const double2*>(Vs + (j0 + jj) * Ddim);
                const double2 a = vr[0], b = vr[1], c = vr[2], d = vr[3];
                o2[0] = fma2(p2, a.x, o2[0]);
                o2[1] = fma2(p2, a.y, o2[1]);
                o2[2] = fma2(p2, b.x, o2[2]);
                o2[3] = fma2(p2, b.y, o2[3]);
                o2[4] = fma2(p2, c.x, o2[4]);
                o2[5] = fma2(p2, c.y, o2[5]);
                o2[6] = fma2(p2, d.x, o2[6]);
                o2[7] = fma2(p2, d.y, o2[7]);
            }
            mi = mnew;
        }
    }

    // Write unnormalized partials
    const size_t pbase = ((size_t)head * SPLIT + sp) * Ndim + n;
    g_Pm[pbase] = mi;
    g_Pl[pbase] = li;
    float4* Pp = reinterpret_cast<float4*>(g_Po + pbase * Ddim);
    #pragma unroll
    for (int i = 0; i < 4; i++) {
        float4 r;
        r.x = lo2(o2[2*i]);   r.y = hi2(o2[2*i]);
        r.z = lo2(o2[2*i+1]); r.w = hi2(o2[2*i+1]);
        Pp[i] = r;
    }
}

// ---------------------------------------------------------------------------
// Kernel 2b: combine split partials -> g_O[b][n][k][d] (+ bias_theta)
// ---------------------------------------------------------------------------
__global__ __launch_bounds__(128) void combine_kernel(const float* __restrict__ bt)
{
    const int head = blockIdx.y;
    const int n    = blockIdx.x * 128 + threadIdx.x;

    float m4[SPLIT], l4[SPLIT];
    #pragma unroll
    for (int s = 0; s < SPLIT; s++) {
        const size_t pbase = ((size_t)head * SPLIT + s) * Ndim + n;
        m4[s] = g_Pm[pbase];
        l4[s] = g_Pl[pbase];
    }
    float M = m4[0];
    #pragma unroll
    for (int s = 1; s < SPLIT; s++) M = fmaxf(M, m4[s]);

    float w4[SPLIT], L = 0.f;
    #pragma unroll
    for (int s = 0; s < SPLIT; s++) {
        w4[s] = ex2f(m4[s] - M);
        L += w4[s] * l4[s];
    }
    const float inv = 1.f / L;

    float o[Ddim];
    #pragma unroll
    for (int d = 0; d < Ddim; d++) o[d] = 0.f;
    #pragma unroll
    for (int s = 0; s < SPLIT; s++) {
        const float4* Pp = reinterpret_cast<const float4*>(
            g_Po + (((size_t)head * SPLIT + s) * Ndim + n) * Ddim);
        #pragma unroll
        for (int i = 0; i < 4; i++) {
            const float4 v = Pp[i];
            o[4*i+0] += w4[s] * v.x;
            o[4*i+1] += w4[s] * v.y;
            o[4*i+2] += w4[s] * v.z;
            o[4*i+3] += w4[s] * v.w;
        }
    }

    const int b = head / Kdim;
    const int k = head % Kdim;
    float* Op = g_O + (((size_t)b * Ndim + n) * Kdim + k) * Ddim;
    #pragma unroll
    for (int i = 0; i < 4; i++) {
        float4 r;
        r.x = o[4*i+0] * inv + bt[k * Ddim + 4*i + 0];
        r.y = o[4*i+1] * inv + bt[k * Ddim + 4*i + 1];
        r.z = o[4*i+2] * inv + bt[k * Ddim + 4*i + 2];
        r.w = o[4*i+3] * inv + bt[k * Ddim + 4*i + 3];
        reinterpret_cast<float4*>(Op)[i] = r;
    }
}

// ---------------------------------------------------------------------------
// Kernel 3: output projection, register-blocked 8 rows/block.
// ---------------------------------------------------------------------------
__global__ __launch_bounds__(128) void out_kernel(const float* __restrict__ t2,
                                                  float* __restrict__ out)
{
    __shared__ __align__(16) float orow[8][Kdim * Ddim];
    const int row0 = blockIdx.x * 8;
    const int e = threadIdx.x;   // 0..127

    #pragma unroll
    for (int r = 0; r < 8; r++)
        orow[r][e] = g_O[(size_t)(row0 + r) * (Kdim * Ddim) + e];
    __syncthreads();

    float acc[8];
    #pragma unroll
    for (int r = 0; r < 8; r++) acc[r] = 0.f;

    const float4* t2v = reinterpret_cast<const float4*>(t2);
    #pragma unroll
    for (int k = 0; k < Kdim; k++) {
        const int base = (k * Edim + e) * 4;
        #pragma unroll
        for (int dq = 0; dq < 4; dq++) {
            const float4 wv = t2v[base + dq];
            #pragma unroll
            for (int r = 0; r < 8; r++) {
                const float4 oo = *reinterpret_cast<const float4*>(&orow[r][k * Ddim + dq * 4]);
                acc[r] += wv.x * oo.x + wv.y * oo.y + wv.z * oo.z + wv.w * oo.w;
            }
        }
    }
    #pragma unroll
    for (int r = 0; r < 8; r++)
        out[(size_t)(row0 + r) * Edim + e] = acc[r];
}

extern "C" void kernel_launch(void* const* d_in, const int* in_sizes, int n_in,
                              void* d_out, int out_size)
{
    const float* x  = (const float*)d_in[0];
    const float* y  = (const float*)d_in[1];
    const float* l1 = (const float*)d_in[2];
    const float* l2 = (const float*)d_in[3];
    const float* t1 = (const float*)d_in[4];
    const float* t2 = (const float*)d_in[5];
    const float* bl = (const float*)d_in[6];
    const float* bt = (const float*)d_in[7];

    proj_kernel<<<Bdim * Mdim / 16, 256>>>(x, y, l1, l2, t1, bl);
    flash_kernel<<<dim3(Ndim / BN, NHEAD, SPLIT), BN>>>();
    combine_kernel<<<dim3(Ndim / 128, NHEAD), 128>>>(bt);
    out_kernel<<<Bdim * Ndim / 8, 128>>>(t2, (float*)d_out);
}